// round 5
// baseline (speedup 1.0000x reference)
#include <cuda_runtime.h>
#include <math.h>

#define NN 200000
#define FF 256
#define CC 8
#define SC 16
#define EE 4000000
#define NSTEP 4
#define G3F 768
#define EPSF 1e-8f
#define MAXCAND 65536
#define STAGE 512
#define NW (NN/4)

#define NB 32
#define NT 1024
#define TT (NB*NT)
#define CHUNK ((NN + NB - 1) / NB)     // 6250
#define PT ((CHUNK + NT - 1) / NT)     // 7

// output layout (float32, concatenated in reference-return order)
#define OUT_OUTPUTS 0        // 4*128*8 = 4096
#define OUT_SELECTS 4096     // 4*128   = 512
#define OUT_STEPS   4608     // 4*8     = 32
#define OUT_HX      4640     // 4*8*256 = 8192   (total 12832)

// ---------------- persistent device state (zeroed at start of every launch) --------
__device__ __align__(16) int g_counts[NN*CC];
__device__ int           g_tflag[NN];
__device__ int           g_touched[NN];
__device__ int           g_ntouched;
__device__ int           g_indeg[NN];
__device__ int           g_startA[NN];
__device__ int           g_cur[NN];
__device__ int           g_csr_src[EE];
__device__ unsigned int  g_member_words[NW];   // 1 byte/node, bit per class
__device__ unsigned char g_entity[NN];
__device__ int           g_cand_pos[NN];
__device__ int           g_ncand;
__device__ int           g_cand_idx[MAXCAND];
__device__ unsigned int  g_cand_vmask[MAXCAND];
__device__ float         g_cand_sims[MAXCAND*CC];
__device__ float g_hx[CC*FF];
__device__ float g_hx_norm[CC*FF];
__device__ float g_inp[CC*FF];
__device__ float g_gi[CC*G3F];
__device__ float g_gh[CC*G3F];
__device__ int   g_last[CC*SC];
__device__ int   g_group[CC*SC];
__device__ int   g_bsum[NB];
__device__ int   g_bbase[NB];
__device__ int           g_bar_count;     // sense-reversal barrier; even #syncs -> self-restoring
__device__ volatile int  g_bar_sense;

// ---------------- grid barrier (all NB blocks resident; uniform call count) ---------
__device__ __forceinline__ void gsync(int& lsense) {
    __syncthreads();
    __threadfence();                       // EVERY thread's writes visible device-wide
    __syncthreads();
    if (threadIdx.x == 0) {
        lsense ^= 1;
        if (atomicAdd(&g_bar_count, 1) == NB - 1) {
            g_bar_count = 0;
            __threadfence();
            g_bar_sense = lsense;
        } else {
            while (g_bar_sense != lsense) { }
            __threadfence();
        }
    }
    __syncthreads();
}

// add node g_last[slot] to class slot/SC; process its in-edges ONLY on first
// membership (atomicOr bit check) -> exactly reproduces reference set semantics.
__device__ __forceinline__ void member_update(int slot, int lane) {
    int node = g_last[slot];
    int c    = slot / SC;
    int skip = 0;
    if (lane == 0) {
        unsigned bit = (1u << c) << ((node & 3) * 8);
        unsigned old = atomicOr(&g_member_words[node >> 2], bit);
        skip = (old & bit) ? 1 : 0;
    }
    skip = __shfl_sync(0xFFFFFFFFu, skip, 0);
    if (skip) return;
    int st  = g_startA[node];
    int deg = g_indeg[node];
    for (int j = lane; j < deg; j += 32) {
        int src = g_csr_src[st + j];
        int old = atomicAdd(&g_counts[src*CC + c], 1);
        if (old == 0 && atomicExch(&g_tflag[src], 1) == 0) {
            int t = atomicAdd(&g_ntouched, 1);
            if (t < NN) g_touched[t] = src;
        }
    }
}

__global__ void __launch_bounds__(NT, 1) mega(
        const int* __restrict__ seeds,
        const int* __restrict__ esrc, const int* __restrict__ edst,
        const float* __restrict__ es,
        const float* __restrict__ W_ih, const float* __restrict__ W_hh,
        const float* __restrict__ b_ih, const float* __restrict__ b_hh,
        float* __restrict__ out) {
    const int tid  = threadIdx.x;
    const int b    = blockIdx.x;
    const int gid  = b * NT + tid;
    const int lane = tid & 31;
    const int gw   = gid >> 5;                 // global warp id (0..1023)
    int lsense = 0;

    __shared__ int      s_scan[NT];
    __shared__ int      s_idx[STAGE];
    __shared__ unsigned s_vm[STAGE];
    __shared__ float    s_sims[STAGE*CC];
    __shared__ unsigned s_nodev[STAGE];

    const int4* edst4 = (const int4*)edst;
    const int4* esrc4 = (const int4*)esrc;

    // ================= Z: zero state + seed-independent init =================
    {
        int4 z4 = {0,0,0,0};
        for (int i = gid; i < NN*CC/4; i += TT) ((int4*)g_counts)[i] = z4;
        for (int i = gid; i < NN; i += TT) {
            g_tflag[i] = 0; g_cand_pos[i] = 0; g_indeg[i] = 0; g_entity[i] = 0;
        }
        for (int i = gid; i < NW; i += TT) g_member_words[i] = 0u;
        if (gid < CC*FF) g_hx[gid] = 0.f;
        if (gid < CC*SC) g_last[gid] = seeds[gid];
        if (gid < NSTEP*CC) out[OUT_STEPS + gid] = 16.0f;
        if (gid == 0) { g_ncand = 0; g_ntouched = 0; }
        for (int q = gid; q < CC*FF; q += TT) {      // pooling for step 0 from seeds
            int c = q >> 8, f = q & 255;
            float s = 0.f;
            for (int j = 0; j < SC; j++) s += es[(size_t)seeds[c*SC + j] * FF + f];
            g_inp[q] = s * (1.f / 16.f);
        }
    }
    gsync(lsense);                                                     // S1

    // ================= H: in-degree histogram =================
    for (int q = gid; q < EE/4; q += TT) {
        int4 d = edst4[q];
        atomicAdd(&g_indeg[d.x], 1); atomicAdd(&g_indeg[d.y], 1);
        atomicAdd(&g_indeg[d.z], 1); atomicAdd(&g_indeg[d.w], 1);
    }
    gsync(lsense);                                                     // S2

    // ================= scan A: block-local sums =================
    int texcl;
    {
        int lim = (b+1)*CHUNK; if (lim > NN) lim = NN;
        int i0  = b*CHUNK + tid*PT;
        int ts  = 0;
        #pragma unroll
        for (int k = 0; k < PT; k++) { int i = i0 + k; if (i < lim) ts += g_indeg[i]; }
        s_scan[tid] = ts;
        __syncthreads();
        for (int off = 1; off < NT; off <<= 1) {
            int v = (tid >= off) ? s_scan[tid - off] : 0;
            __syncthreads();
            s_scan[tid] += v;
            __syncthreads();
        }
        texcl = s_scan[tid] - ts;
        if (tid == NT-1) g_bsum[b] = s_scan[tid];
    }
    gsync(lsense);                                                     // S3

    // ================= scan B: block base offsets (block 0, one warp) =========
    if (b == 0 && tid < NB) {
        int v = g_bsum[tid];
        int incl = v;
        #pragma unroll
        for (int off = 1; off < NB; off <<= 1) {
            int t2 = __shfl_up_sync(0xFFFFFFFFu, incl, off);
            if (lane >= off) incl += t2;
        }
        g_bbase[tid] = incl - v;
    }
    gsync(lsense);                                                     // S4

    // ================= scan C: per-node start offsets + cursors =================
    {
        int lim = (b+1)*CHUNK; if (lim > NN) lim = NN;
        int i0  = b*CHUNK + tid*PT;
        int run = g_bbase[b] + texcl;
        #pragma unroll
        for (int k = 0; k < PT; k++) {
            int i = i0 + k;
            if (i < lim) { g_startA[i] = run; g_cur[i] = run; run += g_indeg[i]; }
        }
    }
    gsync(lsense);                                                     // S5

    // ================= scatter: build CSR (dst -> list of src) =================
    for (int q = gid; q < EE/4; q += TT) {
        int4 ss = esrc4[q];
        int4 dd = edst4[q];
        int p;
        p = atomicAdd(&g_cur[dd.x], 1); g_csr_src[p] = ss.x;
        p = atomicAdd(&g_cur[dd.y], 1); g_csr_src[p] = ss.y;
        p = atomicAdd(&g_cur[dd.z], 1); g_csr_src[p] = ss.z;
        p = atomicAdd(&g_cur[dd.w], 1); g_csr_src[p] = ss.w;
    }
    gsync(lsense);                                                     // S6

    // ================= step loop =================
    for (int s = 0; s < NSTEP; s++) {
        int mm = (s == 0) ? 3 : 2;

        // ---- P1: GRU gates (warp per W row) + (s==0) seed membership/counts ----
        for (int r = gw; r < 2*G3F; r += TT/32) {
            int half = r / G3F, k = r % G3F;
            const float* W = half ? W_hh : W_ih;
            const float* X = half ? g_hx : g_inp;
            const float* B = half ? b_hh : b_ih;
            float*       O = half ? g_gh : g_gi;
            float w[8];
            #pragma unroll
            for (int j = 0; j < 8; j++) w[j] = W[(size_t)k*FF + j*32 + lane];
            float bias = B[k];
            for (int c = 0; c < CC; c++) {
                float p = 0.f;
                #pragma unroll
                for (int j = 0; j < 8; j++) p += w[j] * X[c*FF + j*32 + lane];
                #pragma unroll
                for (int o = 16; o; o >>= 1) p += __shfl_xor_sync(0xFFFFFFFFu, p, o);
                if (lane == 0) O[c*G3F + k] = p + bias;
            }
        }
        if (s == 0) {
            if (gid < CC*SC) g_entity[g_last[gid]] = 1;
            if (gw < CC*SC) member_update(gw, lane);
        }
        gsync(lsense);                                                 // per-step S a

        // ---- P2: combine (block 0, warps 0-7) | candidate detection (rest) ----
        if (b == 0 && tid < 256) {
            int c = tid >> 5;
            float hv[8], ssum = 0.f;
            #pragma unroll
            for (int j = 0; j < 8; j++) {
                int f = j*32 + lane;
                float ir = g_gi[c*G3F + f], iz = g_gi[c*G3F + FF + f], in = g_gi[c*G3F + 2*FF + f];
                float hr = g_gh[c*G3F + f], hz = g_gh[c*G3F + FF + f], hn = g_gh[c*G3F + 2*FF + f];
                float h  = g_hx[c*FF + f];
                float rr = 1.f / (1.f + expf(-(ir + hr)));
                float zz = 1.f / (1.f + expf(-(iz + hz)));
                float nv = tanhf(in + rr * hn);
                hv[j] = (1.f - zz) * nv + zz * h;
                g_hx[c*FF + f] = hv[j];
                out[OUT_HX + s*CC*FF + c*FF + f] = hv[j];
                ssum += hv[j] * hv[j];
            }
            #pragma unroll
            for (int o = 16; o; o >>= 1) ssum += __shfl_xor_sync(0xFFFFFFFFu, ssum, o);
            float inv = 1.f / (sqrtf(ssum) + EPSF);
            #pragma unroll
            for (int j = 0; j < 8; j++) g_hx_norm[c*FF + j*32 + lane] = hv[j] * inv;
        } else {
            int dt = gid - 256, DTT = TT - 256;
            int nt = g_ntouched; if (nt > NN) nt = NN;
            for (int e = dt; e < nt; e += DTT) {
                int src = g_touched[e];
                if (g_entity[src]) continue;
                int4 a  = ((const int4*)g_counts)[src*2];
                int4 bb = ((const int4*)g_counts)[src*2 + 1];
                unsigned vm = 0;
                vm |= (unsigned)(a.x  >= mm);
                vm |= (unsigned)(a.y  >= mm) << 1;
                vm |= (unsigned)(a.z  >= mm) << 2;
                vm |= (unsigned)(a.w  >= mm) << 3;
                vm |= (unsigned)(bb.x >= mm) << 4;
                vm |= (unsigned)(bb.y >= mm) << 5;
                vm |= (unsigned)(bb.z >= mm) << 6;
                vm |= (unsigned)(bb.w >= mm) << 7;
                if (vm) {
                    int pos = atomicAdd(&g_ncand, 1);
                    if (pos < MAXCAND) {
                        g_cand_idx[pos] = src;
                        g_cand_vmask[pos] = vm;
                        g_cand_pos[src] = pos + 1;
                    }
                }
            }
        }
        gsync(lsense);                                                 // per-step S b

        // ---- P3: sims for candidates (warp per candidate) ----
        {
            int nc = g_ncand; if (nc > MAXCAND) nc = MAXCAND;
            for (int w = gw; w < nc; w += TT/32) {
                int src = g_cand_idx[w];
                float ssum = 0.f, pc[CC];
                #pragma unroll
                for (int c = 0; c < CC; c++) pc[c] = 0.f;
                #pragma unroll
                for (int j = 0; j < 8; j++) {
                    float v = es[(size_t)src*FF + j*32 + lane];
                    ssum += v * v;
                    #pragma unroll
                    for (int c = 0; c < CC; c++) pc[c] += v * g_hx_norm[c*FF + j*32 + lane];
                }
                #pragma unroll
                for (int o = 16; o; o >>= 1) ssum += __shfl_xor_sync(0xFFFFFFFFu, ssum, o);
                float inv = 1.f / (sqrtf(ssum) + EPSF);
                #pragma unroll
                for (int c = 0; c < CC; c++) {
                    float p = pc[c];
                    #pragma unroll
                    for (int o = 16; o; o >>= 1) p += __shfl_xor_sync(0xFFFFFFFFu, p, o);
                    if (lane == 0) g_cand_sims[w*CC + c] = p * inv * 0.5f + 0.5f;
                }
            }
        }
        gsync(lsense);                                                 // per-step S c

        // ---- P4: block 0 — staged top-16 per class + finalize ----
        if (b == 0) {
            int n = g_ncand; if (n > MAXCAND) n = MAXCAND;
            bool staged = (n <= STAGE);
            if (staged && tid < n) {
                s_idx[tid] = g_cand_idx[tid];
                s_vm[tid]  = g_cand_vmask[tid];
                #pragma unroll
                for (int c = 0; c < CC; c++) s_sims[tid*CC + c] = g_cand_sims[tid*CC + c];
            }
            if (tid < STAGE) {
                int p = g_cand_pos[tid];
                s_nodev[tid] = p ? g_cand_vmask[p-1] : 0u;
            }
            __syncthreads();
            if (tid < 256) {
                int c = tid >> 5;
                unsigned long long prev = 0xFFFFFFFFFFFFFFFFull;
                int nsel = 0;
                for (int r = 0; r < SC; r++) {
                    unsigned long long best = 0;
                    for (int i = lane; i < n; i += 32) {
                        unsigned vm = staged ? s_vm[i] : g_cand_vmask[i];
                        if ((vm >> c) & 1) {
                            float prob = staged ? s_sims[i*CC + c] : g_cand_sims[i*CC + c];
                            unsigned u = __float_as_uint(prob);
                            u = (u >> 31) ? ~u : (u | 0x80000000u);
                            int idxv = staged ? s_idx[i] : g_cand_idx[i];
                            unsigned long long key =
                                ((unsigned long long)u << 32) | (unsigned)(~(unsigned)idxv);
                            if (key < prev && key > best) best = key;
                        }
                    }
                    #pragma unroll
                    for (int o = 16; o; o >>= 1) {
                        unsigned long long v = __shfl_xor_sync(0xFFFFFFFFu, best, o);
                        if (v > best) best = v;
                    }
                    if (!best) break;
                    if (lane == 0) g_group[c*SC + r] = (int)(~(unsigned)best);
                    prev = best; nsel = r + 1;
                }
                // fill remaining slots with smallest-index invalid-for-c nodes
                int need = SC - nsel, slot = nsel, w = 0;
                while (need > 0 && w < NN/32) {
                    int j = w*32 + lane;
                    int valid;
                    if (j < STAGE) valid = (s_nodev[j] >> c) & 1;
                    else { int p = g_cand_pos[j]; valid = p ? ((g_cand_vmask[p-1] >> c) & 1) : 0; }
                    unsigned bal = __ballot_sync(0xFFFFFFFFu, !valid);
                    if (lane == 0) {
                        while (bal && need) {
                            int bp = __ffs(bal) - 1; bal &= bal - 1;
                            g_group[c*SC + slot] = w*32 + bp;
                            slot++; need--;
                        }
                    }
                    need = __shfl_sync(0xFFFFFFFFu, need, 0);
                    slot = __shfl_sync(0xFFFFFFFFu, slot, 0);
                    w++;
                }
                __syncwarp();
                if (lane < SC)
                    out[OUT_SELECTS + s*(CC*SC) + c*SC + lane] = (float)g_group[c*SC + lane];
            }
            __syncthreads();
            {   // outputs = probs[flat] (1024 elements exactly)
                int flat = tid >> 3, c2 = tid & 7;
                int node = g_group[flat];
                int p = g_cand_pos[node];
                out[OUT_OUTPUTS + s*(CC*SC*CC) + tid] =
                    p ? g_cand_sims[(p-1)*CC + c2] : 0.f;
            }
            __syncthreads();
            if (tid < CC*SC) {
                int node = g_group[tid];
                g_entity[node] = 1;
                g_last[tid] = node;
            }
            for (int i = tid; i < n; i += NT) g_cand_pos[g_cand_idx[i]] = 0;
            __syncthreads();
            if (tid == 0) g_ncand = 0;
        }
        gsync(lsense);                                                 // per-step S d

        // ---- P5: pooling for next step + incremental count update ----
        if (s < NSTEP-1) {
            for (int q = gid; q < CC*FF; q += TT) {
                int c = q >> 8, f = q & 255;
                float sum = 0.f;
                for (int j = 0; j < SC; j++) sum += es[(size_t)g_last[c*SC + j]*FF + f];
                g_inp[q] = sum * (1.f / 16.f);
            }
            if (gw < CC*SC) member_update(gw, lane);
        }
        gsync(lsense);                                                 // per-step S e
    }
    // total gsyncs: 6 + 4*5 = 26 (even) -> barrier state self-restores
}

// ---------------- launch -----------------------------------------------------------
extern "C" void kernel_launch(void* const* d_in, const int* in_sizes, int n_in,
                              void* d_out, int out_size) {
    const int*   seeds = (const int*)d_in[0];
    const int*   esrc  = (const int*)d_in[1];
    const int*   edst  = (const int*)d_in[2];
    const float* es    = (const float*)d_in[3];
    const float* W_ih  = (const float*)d_in[4];
    const float* W_hh  = (const float*)d_in[5];
    const float* b_ih  = (const float*)d_in[6];
    const float* b_hh  = (const float*)d_in[7];
    float* out = (float*)d_out;
    (void)in_sizes; (void)n_in; (void)out_size;
    mega<<<NB, NT>>>(seeds, esrc, edst, es, W_ih, W_hh, b_ih, b_hh, out);
}